// round 2
// baseline (speedup 1.0000x reference)
#include <cuda_runtime.h>
#include <math.h>

#define Bv     64
#define Hh     56
#define Wd     56
#define Cc     256
#define WSZ    7
#define SHIFT  3
#define HEADS  8
#define Nn     49
#define HID    1024
#define Ltok   (Hh*Wd)        // 3136
#define Mtok   (Bv*Ltok)      // 200704
#define BWIN   (Bv*64)        // 4096 windows total
#define HD     32

// ---------------- scratch (static device allocations; no cudaMalloc) --------
__device__ float g_y   [(size_t)Mtok*Cc];     // LN output / window-ordered tokens
__device__ float g_qkv [(size_t)Mtok*3*Cc];   // qkv projections
__device__ float g_o   [(size_t)Mtok*Cc];     // attention output (window order)
__device__ float g_xres[(size_t)Mtok*Cc];     // x + attn branch (pixel order)
__device__ float g_h1  [(size_t)Mtok*HID];    // fc1+gelu output

// token t (window order) -> pixel row (original order), accounting for the
// cyclic shift. Used for both the LN1 gather and the proj-output scatter.
__device__ __forceinline__ size_t dest_row(int t) {
    int b_ = t / Nn, n = t - b_*Nn;
    int b  = b_ >> 6, w = b_ & 63;
    int wh = w >> 3, wc = w & 7;
    int i  = n / WSZ, j = n - i*WSZ;
    int sh = wh*WSZ + i + SHIFT; if (sh >= Hh) sh -= Hh;
    int sw = wc*WSZ + j + SHIFT; if (sw >= Wd) sw -= Wd;
    return (size_t)b*Ltok + (size_t)sh*Wd + sw;
}

// ---------------- LayerNorm (one block per token, 256 threads) --------------
template<bool MAP>
__global__ __launch_bounds__(256) void ln_k(const float* __restrict__ x,
                                            const float* __restrict__ g,
                                            const float* __restrict__ bta,
                                            float* __restrict__ y)
{
    int t = blockIdx.x;
    int c = threadIdx.x;
    size_t src = MAP ? dest_row(t) : (size_t)t;
    float v = x[src*Cc + c];

    __shared__ float r1[8], r2[8];
    float s = v;
    #pragma unroll
    for (int o = 16; o; o >>= 1) s += __shfl_xor_sync(0xffffffffu, s, o);
    if ((c & 31) == 0) r1[c >> 5] = s;
    __syncthreads();
    float mean = 0.f;
    #pragma unroll
    for (int i = 0; i < 8; i++) mean += r1[i];
    mean *= (1.f/256.f);

    float d = v - mean;
    float q = d*d;
    #pragma unroll
    for (int o = 16; o; o >>= 1) q += __shfl_xor_sync(0xffffffffu, q, o);
    if ((c & 31) == 0) r2[c >> 5] = q;
    __syncthreads();
    float var = 0.f;
    #pragma unroll
    for (int i = 0; i < 8; i++) var += r2[i];
    var *= (1.f/256.f);

    y[(size_t)t*Cc + c] = d * rsqrtf(var + 1e-5f) * g[c] + bta[c];
}

// ---------------- SGEMM: C = epi(A[M,K] @ W[Nc,K]^T + bias) -----------------
// EPI 0: store   1: fast-gelu   2: C = res + v   3: scatter rows via dest_row, C = res + v
template<int EPI>
__global__ __launch_bounds__(256) void gemm_k(const float* __restrict__ A,
                                              const float* __restrict__ W,
                                              const float* __restrict__ bias,
                                              float* __restrict__ C,
                                              int K, int Nc,
                                              const float* __restrict__ res)
{
    __shared__ float As[16][128];
    __shared__ float Ws[16][128];
    const int bm  = blockIdx.y * 128;
    const int bn  = blockIdx.x * 128;
    const int tid = threadIdx.x;

    float acc[8][8];
    #pragma unroll
    for (int i = 0; i < 8; i++)
        #pragma unroll
        for (int j = 0; j < 8; j++) acc[i][j] = 0.f;

    const int ty = tid >> 4, tx = tid & 15;

    for (int k0 = 0; k0 < K; k0 += 16) {
        #pragma unroll
        for (int l = 0; l < 2; l++) {
            int f  = tid + l*256;
            int r  = f >> 2;
            int c4 = (f & 3) << 2;
            float4 av = *(const float4*)(A + (size_t)(bm + r)*K + k0 + c4);
            As[c4+0][r] = av.x; As[c4+1][r] = av.y; As[c4+2][r] = av.z; As[c4+3][r] = av.w;
            float4 wv = *(const float4*)(W + (size_t)(bn + r)*K + k0 + c4);
            Ws[c4+0][r] = wv.x; Ws[c4+1][r] = wv.y; Ws[c4+2][r] = wv.z; Ws[c4+3][r] = wv.w;
        }
        __syncthreads();
        #pragma unroll
        for (int kk = 0; kk < 16; kk++) {
            float ra[8], rb[8];
            #pragma unroll
            for (int i = 0; i < 8; i++) ra[i] = As[kk][ty*8 + i];
            #pragma unroll
            for (int j = 0; j < 8; j++) rb[j] = Ws[kk][tx*8 + j];
            #pragma unroll
            for (int i = 0; i < 8; i++)
                #pragma unroll
                for (int j = 0; j < 8; j++)
                    acc[i][j] += ra[i]*rb[j];
        }
        __syncthreads();
    }

    const int row0 = bm + ty*8, col0 = bn + tx*8;
    #pragma unroll
    for (int i = 0; i < 8; i++) {
        int row = row0 + i;
        size_t orow = (EPI == 3) ? dest_row(row) : (size_t)row;
        #pragma unroll
        for (int j = 0; j < 8; j++) {
            int col = col0 + j;
            float v = acc[i][j] + bias[col];
            size_t idx = orow*(size_t)Nc + col;
            if (EPI == 1)      { v = v / (1.f + __expf(-1.702f*v)); C[idx] = v; }
            else if (EPI == 2) C[idx] = res[idx] + v;
            else if (EPI == 3) C[idx] = res[idx] + v;
            else               C[idx] = v;
        }
    }
}

// ---------------- windowed attention: one block per (window, head) ----------
__global__ __launch_bounds__(256) void attn_k(const float* __restrict__ qkv,
                                              const float* __restrict__ rpb,
                                              const int*   __restrict__ rel,
                                              const float* __restrict__ mask,
                                              float* __restrict__ o)
{
    int bh   = blockIdx.x;
    int b_   = bh >> 3, head = bh & 7;
    __shared__ float q [Nn][HD];
    __shared__ float kt[HD][Nn];
    __shared__ float v [Nn][HD];
    __shared__ float s [Nn][Nn];
    int tid = threadIdx.x;
    const float scale = 0.17677669529663687f;   // 32^-0.5

    for (int idx = tid; idx < Nn*HD; idx += 256) {
        int n = idx >> 5, d = idx & 31;
        size_t base = ((size_t)(b_*Nn + n))*768 + head*HD + d;
        q [n][d] = qkv[base] * scale;
        kt[d][n] = qkv[base + 256];
        v [n][d] = qkv[base + 512];
    }
    __syncthreads();

    int wIdx = b_ & 63;
    const float* mrow = mask + (size_t)wIdx*Nn*Nn;
    for (int idx = tid; idx < Nn*Nn; idx += 256) {
        int n = idx / Nn, m = idx - n*Nn;
        float acc = 0.f;
        #pragma unroll
        for (int d = 0; d < HD; d++) acc += q[n][d]*kt[d][m];
        acc += rpb[rel[idx]*HEADS + head] + mrow[idx];
        s[n][m] = acc;
    }
    __syncthreads();

    int warp = tid >> 5, lane = tid & 31;
    for (int n = warp; n < Nn; n += 8) {
        float mx = -1e30f;
        for (int m = lane; m < Nn; m += 32) mx = fmaxf(mx, s[n][m]);
        #pragma unroll
        for (int o2 = 16; o2; o2 >>= 1) mx = fmaxf(mx, __shfl_xor_sync(0xffffffffu, mx, o2));
        float sum = 0.f;
        for (int m = lane; m < Nn; m += 32) { float e = __expf(s[n][m]-mx); s[n][m] = e; sum += e; }
        #pragma unroll
        for (int o2 = 16; o2; o2 >>= 1) sum += __shfl_xor_sync(0xffffffffu, sum, o2);
        float inv = 1.f/sum;
        for (int m = lane; m < Nn; m += 32) s[n][m] *= inv;
    }
    __syncthreads();

    for (int idx = tid; idx < Nn*HD; idx += 256) {
        int n = idx >> 5, d = idx & 31;
        float acc = 0.f;
        #pragma unroll
        for (int m = 0; m < Nn; m++) acc += s[n][m]*v[m][d];
        o[((size_t)(b_*Nn + n))*Cc + head*HD + d] = acc;
    }
}

// ---------------- launch --------------------------------------------------
extern "C" void kernel_launch(void* const* d_in, const int* in_sizes, int n_in,
                              void* d_out, int out_size)
{
    const float* x      = (const float*)d_in[0];
    const float* n1g    = (const float*)d_in[1];
    const float* n1b    = (const float*)d_in[2];
    const float* qkv_w  = (const float*)d_in[3];
    const float* qkv_b  = (const float*)d_in[4];
    const float* rpb    = (const float*)d_in[5];
    const float* proj_w = (const float*)d_in[6];
    const float* proj_b = (const float*)d_in[7];
    const float* n2g    = (const float*)d_in[8];
    const float* n2b    = (const float*)d_in[9];
    const float* fc1_w  = (const float*)d_in[10];
    const float* fc1_b  = (const float*)d_in[11];
    const float* fc2_w  = (const float*)d_in[12];
    const float* fc2_b  = (const float*)d_in[13];
    const int*   rel    = (const int*)d_in[14];
    const float* mask   = (const float*)d_in[15];
    float* out = (float*)d_out;

    float *y, *qkvb, *ob, *xres, *h1;
    cudaGetSymbolAddress((void**)&y,    g_y);
    cudaGetSymbolAddress((void**)&qkvb, g_qkv);
    cudaGetSymbolAddress((void**)&ob,   g_o);
    cudaGetSymbolAddress((void**)&xres, g_xres);
    cudaGetSymbolAddress((void**)&h1,   g_h1);

    // 1) LN1 + cyclic shift + window partition (gather)
    ln_k<true><<<Mtok, 256>>>(x, n1g, n1b, y);
    // 2) QKV projection: (M,256) @ (768,256)^T
    gemm_k<0><<<dim3(768/128, Mtok/128), 256>>>(y, qkv_w, qkv_b, qkvb, 256, 768, nullptr);
    // 3) windowed attention with rel-pos bias + shift mask
    attn_k<<<BWIN*HEADS, 256>>>(qkvb, rpb, rel, mask, ob);
    // 4) output proj + window reverse + reverse shift + residual (scatter)
    gemm_k<3><<<dim3(256/128, Mtok/128), 256>>>(ob, proj_w, proj_b, xres, 256, 256, x);
    // 5) LN2
    ln_k<false><<<Mtok, 256>>>(xres, n2g, n2b, y);
    // 6) FC1 + fast-gelu
    gemm_k<1><<<dim3(1024/128, Mtok/128), 256>>>(y, fc1_w, fc1_b, h1, 256, 1024, nullptr);
    // 7) FC2 + residual -> final output
    gemm_k<2><<<dim3(256/128, Mtok/128), 256>>>(h1, fc2_w, fc2_b, out, 1024, 256, xres);
}

// round 6
// speedup vs baseline: 1.9691x; 1.9691x over previous
#include <cuda_runtime.h>
#include <cuda_bf16.h>
#include <cstdint>
#include <math.h>

#define Bv     64
#define Hh     56
#define Wd     56
#define Cc     256
#define WSZ    7
#define SHIFT  3
#define HEADS  8
#define Nn     49
#define HID    1024
#define Ltok   (Hh*Wd)        // 3136
#define Mtok   (Bv*Ltok)      // 200704
#define BWIN   (Bv*64)        // 4096 windows
#define HD     32

// ---------------- scratch (static device arrays; no cudaMalloc) -------------
__device__ __nv_bfloat16 g_ybf  [(size_t)Mtok*Cc];
__device__ __nv_bfloat16 g_qkvbf[(size_t)Mtok*3*Cc];
__device__ __nv_bfloat16 g_obf  [(size_t)Mtok*Cc];
__device__ __nv_bfloat16 g_h1bf [(size_t)Mtok*HID];
__device__ float         g_xres [(size_t)Mtok*Cc];
__device__ __nv_bfloat16 g_wbf  [786432];   // qkv|proj|fc1|fc2 bf16 weights

#define OFF_QKV  0
#define OFF_PROJ 196608
#define OFF_FC1  262144
#define OFF_FC2  524288

// ---------------- PTX helpers (sm_80-era only; no tcgen05) ------------------
__device__ __forceinline__ uint32_t smem_to_u32(const void* p) {
    uint32_t a;
    asm("{ .reg .u64 t; cvta.to.shared.u64 t, %1; cvt.u32.u64 %0, t; }" : "=r"(a) : "l"(p));
    return a;
}
#define CP_ASYNC16(dst, src) asm volatile("cp.async.cg.shared.global [%0], [%1], 16;" :: "r"((uint32_t)(dst)), "l"(src) : "memory")
#define CP_COMMIT()          asm volatile("cp.async.commit_group;" ::: "memory")
#define CP_WAIT(n)           asm volatile("cp.async.wait_group %0;" :: "n"(n) : "memory")

#define LDSM_X4(r, addr) \
    asm volatile("ldmatrix.sync.aligned.m8n8.x4.shared.b16 {%0,%1,%2,%3}, [%4];" \
        : "=r"((r)[0]),"=r"((r)[1]),"=r"((r)[2]),"=r"((r)[3]) : "r"(addr))

#define MMA16816(c, a, b0, b1) \
    asm volatile("mma.sync.aligned.m16n8k16.row.col.f32.bf16.bf16.f32 " \
        "{%0,%1,%2,%3},{%4,%5,%6,%7},{%8,%9},{%0,%1,%2,%3};" \
        : "+f"((c)[0]),"+f"((c)[1]),"+f"((c)[2]),"+f"((c)[3]) \
        : "r"((a)[0]),"r"((a)[1]),"r"((a)[2]),"r"((a)[3]), "r"(b0),"r"(b1))

// token t (window order) -> pixel row (original order), incl. cyclic shift
__device__ __forceinline__ size_t dest_row(int t) {
    int b_ = t / Nn, n = t - b_*Nn;
    int b  = b_ >> 6, w = b_ & 63;
    int wh = w >> 3, wc = w & 7;
    int i  = n / WSZ, j = n - i*WSZ;
    int sh = wh*WSZ + i + SHIFT; if (sh >= Hh) sh -= Hh;
    int sw = wc*WSZ + j + SHIFT; if (sw >= Wd) sw -= Wd;
    return (size_t)b*Ltok + (size_t)sh*Wd + sw;
}

// ---------------- weight fp32 -> bf16 ---------------------------------------
__global__ void cvt_k(const float* __restrict__ s, __nv_bfloat16* __restrict__ d, int n) {
    int i = blockIdx.x*blockDim.x + threadIdx.x;
    if (i < n) d[i] = __float2bfloat16(s[i]);
}

// ---------------- LayerNorm -> bf16 -----------------------------------------
template<bool MAP>
__global__ __launch_bounds__(256) void ln_k(const float* __restrict__ x,
                                            const float* __restrict__ g,
                                            const float* __restrict__ bta,
                                            __nv_bfloat16* __restrict__ y)
{
    int t = blockIdx.x, c = threadIdx.x;
    size_t src = MAP ? dest_row(t) : (size_t)t;
    float v = x[src*Cc + c];
    __shared__ float r1[8], r2[8];
    float s = v;
    #pragma unroll
    for (int o = 16; o; o >>= 1) s += __shfl_xor_sync(0xffffffffu, s, o);
    if ((c & 31) == 0) r1[c >> 5] = s;
    __syncthreads();
    float mean = 0.f;
    #pragma unroll
    for (int i = 0; i < 8; i++) mean += r1[i];
    mean *= (1.f/256.f);
    float d = v - mean, q = d*d;
    #pragma unroll
    for (int o = 16; o; o >>= 1) q += __shfl_xor_sync(0xffffffffu, q, o);
    if ((c & 31) == 0) r2[c >> 5] = q;
    __syncthreads();
    float var = 0.f;
    #pragma unroll
    for (int i = 0; i < 8; i++) var += r2[i];
    var *= (1.f/256.f);
    y[(size_t)t*Cc + c] = __float2bfloat16(d * rsqrtf(var + 1e-5f) * g[c] + bta[c]);
}

// ---------------- HMMA GEMM: C = epi(A[M,K]bf16 @ W[N,K]bf16^T + bias) ------
// EPI 0: bf16 store  1: gelu->bf16  2: fp32 res+v  3: scatter rows, fp32 res+v
// CTA tile 128x128, BK=32, 8 warps (4 m x 2 n), warp tile 32x64.
#define LDK 40                 // padded row stride (halves): 80B -> ldmatrix conflict-free
#define ABUF (128*LDK)         // halves per buffer

template<int EPI>
__global__ __launch_bounds__(256) void hgemm(const __nv_bfloat16* __restrict__ A,
                                             const __nv_bfloat16* __restrict__ W,
                                             const float* __restrict__ bias,
                                             int K, int Ntot,
                                             void* __restrict__ Cout,
                                             const float* __restrict__ res)
{
    __shared__ __align__(16) __nv_bfloat16 As[2][ABUF];
    __shared__ __align__(16) __nv_bfloat16 Bs[2][ABUF];

    const int tid = threadIdx.x, warp = tid >> 5, lane = tid & 31;
    const int wm = warp & 3, wn = warp >> 2;
    const int bm = blockIdx.y * 128, bn = blockIdx.x * 128;

    const uint32_t aB = smem_to_u32(As), bB = smem_to_u32(Bs);

    // per-lane ldmatrix tile offsets
    const int t8 = lane >> 3, lr = lane & 7;
    const int a_row  = wm*32 + (t8 & 1)*8 + lr;     // + mt*16
    const int a_col  = (t8 >> 1)*8;                 // + ks*16
    const int b_row  = wn*64 + (t8 >> 1)*8 + lr;    // + pair*16
    const int b_col  = (t8 & 1)*8;                  // + ks*16

    // cp.async source/dest indices (2 chunks each for A and B per thread)
    const int cr = tid >> 2, ccol = (tid & 3) * 8;  // rows 0..63, second pass +64

    float acc[2][8][4];
    #pragma unroll
    for (int mt = 0; mt < 2; mt++)
        #pragma unroll
        for (int nt = 0; nt < 8; nt++)
            #pragma unroll
            for (int j = 0; j < 4; j++) acc[mt][nt][j] = 0.f;

    const int nk = K >> 5;

    // prologue: load tile 0
    {
        #pragma unroll
        for (int l = 0; l < 2; l++) {
            int r = cr + l*64;
            CP_ASYNC16(aB + (r*LDK + ccol)*2, A + (size_t)(bm + r)*K + ccol);
            CP_ASYNC16(bB + (r*LDK + ccol)*2, W + (size_t)(bn + r)*K + ccol);
        }
        CP_COMMIT();
    }

    for (int i = 0; i < nk; i++) {
        if (i + 1 < nk) {
            const int nb = (i + 1) & 1;
            const int k0 = (i + 1) << 5;
            #pragma unroll
            for (int l = 0; l < 2; l++) {
                int r = cr + l*64;
                CP_ASYNC16(aB + (nb*ABUF + r*LDK + ccol)*2, A + (size_t)(bm + r)*K + k0 + ccol);
                CP_ASYNC16(bB + (nb*ABUF + r*LDK + ccol)*2, W + (size_t)(bn + r)*K + k0 + ccol);
            }
            CP_COMMIT();
            CP_WAIT(1);
        } else {
            CP_WAIT(0);
        }
        __syncthreads();

        const uint32_t aS = aB + (i & 1)*ABUF*2;
        const uint32_t bS = bB + (i & 1)*ABUF*2;
        #pragma unroll
        for (int ks = 0; ks < 2; ks++) {
            uint32_t afr[2][4], bfr[4][4];
            #pragma unroll
            for (int mt = 0; mt < 2; mt++)
                LDSM_X4(afr[mt], aS + (uint32_t)(((a_row + mt*16)*LDK) + ks*16 + a_col)*2);
            #pragma unroll
            for (int pr = 0; pr < 4; pr++)
                LDSM_X4(bfr[pr], bS + (uint32_t)(((b_row + pr*16)*LDK) + ks*16 + b_col)*2);
            #pragma unroll
            for (int mt = 0; mt < 2; mt++)
                #pragma unroll
                for (int nt = 0; nt < 8; nt++)
                    MMA16816(acc[mt][nt], afr[mt], bfr[nt >> 1][(nt & 1)*2], bfr[nt >> 1][(nt & 1)*2 + 1]);
        }
        __syncthreads();
    }

    // epilogue straight from register accumulators
    const int qr = lane >> 2, qc = (lane & 3) * 2;
    #pragma unroll
    for (int mt = 0; mt < 2; mt++) {
        #pragma unroll
        for (int h = 0; h < 2; h++) {
            int row = bm + wm*32 + mt*16 + qr + h*8;
            size_t orow = (EPI == 3) ? dest_row(row) : (size_t)row;
            #pragma unroll
            for (int nt = 0; nt < 8; nt++) {
                int col = bn + wn*64 + nt*8 + qc;
                float v0 = acc[mt][nt][h*2 + 0] + bias[col];
                float v1 = acc[mt][nt][h*2 + 1] + bias[col + 1];
                if (EPI == 0) {
                    __nv_bfloat162 p; p.x = __float2bfloat16(v0); p.y = __float2bfloat16(v1);
                    *(__nv_bfloat162*)((__nv_bfloat16*)Cout + (size_t)row*Ntot + col) = p;
                } else if (EPI == 1) {
                    v0 = v0 / (1.f + __expf(-1.702f*v0));
                    v1 = v1 / (1.f + __expf(-1.702f*v1));
                    __nv_bfloat162 p; p.x = __float2bfloat16(v0); p.y = __float2bfloat16(v1);
                    *(__nv_bfloat162*)((__nv_bfloat16*)Cout + (size_t)row*Ntot + col) = p;
                } else {
                    size_t gi = orow*(size_t)Ntot + col;
                    float2 p; p.x = res[gi] + v0; p.y = res[gi + 1] + v1;
                    *(float2*)((float*)Cout + gi) = p;
                }
            }
        }
    }
}

// ---------------- windowed attention (bf16 I/O, fp32 math) ------------------
__global__ __launch_bounds__(256) void attn_k(const __nv_bfloat16* __restrict__ qkv,
                                              const float* __restrict__ rpb,
                                              const int*   __restrict__ rel,
                                              const float* __restrict__ mask,
                                              __nv_bfloat16* __restrict__ o)
{
    int bh = blockIdx.x;
    int b_ = bh >> 3, head = bh & 7;
    __shared__ float q [Nn][HD];
    __shared__ float kt[HD][Nn];
    __shared__ float v [Nn][HD];
    __shared__ float s [Nn][Nn];
    int tid = threadIdx.x;
    const float scale = 0.17677669529663687f;

    for (int idx = tid; idx < Nn*HD; idx += 256) {
        int n = idx >> 5, d = idx & 31;
        size_t base = ((size_t)(b_*Nn + n))*768 + head*HD + d;
        q [n][d] = __bfloat162float(qkv[base]) * scale;
        kt[d][n] = __bfloat162float(qkv[base + 256]);
        v [n][d] = __bfloat162float(qkv[base + 512]);
    }
    __syncthreads();

    int wIdx = b_ & 63;
    const float* mrow = mask + (size_t)wIdx*Nn*Nn;
    for (int idx = tid; idx < Nn*Nn; idx += 256) {
        int n = idx / Nn, m = idx - n*Nn;
        float acc = 0.f;
        #pragma unroll
        for (int d = 0; d < HD; d++) acc += q[n][d]*kt[d][m];
        s[n][m] = acc + rpb[rel[idx]*HEADS + head] + mrow[idx];
    }
    __syncthreads();

    int warp = tid >> 5, lane = tid & 31;
    for (int n = warp; n < Nn; n += 8) {
        float mx = -1e30f;
        for (int m = lane; m < Nn; m += 32) mx = fmaxf(mx, s[n][m]);
        #pragma unroll
        for (int o2 = 16; o2; o2 >>= 1) mx = fmaxf(mx, __shfl_xor_sync(0xffffffffu, mx, o2));
        float sum = 0.f;
        for (int m = lane; m < Nn; m += 32) { float e = __expf(s[n][m]-mx); s[n][m] = e; sum += e; }
        #pragma unroll
        for (int o2 = 16; o2; o2 >>= 1) sum += __shfl_xor_sync(0xffffffffu, sum, o2);
        float inv = 1.f/sum;
        for (int m = lane; m < Nn; m += 32) s[n][m] *= inv;
    }
    __syncthreads();

    for (int idx = tid; idx < Nn*HD; idx += 256) {
        int n = idx >> 5, d = idx & 31;
        float acc = 0.f;
        #pragma unroll
        for (int m = 0; m < Nn; m++) acc += s[n][m]*v[m][d];
        o[((size_t)(b_*Nn + n))*Cc + head*HD + d] = __float2bfloat16(acc);
    }
}

// ---------------- launch ----------------------------------------------------
extern "C" void kernel_launch(void* const* d_in, const int* in_sizes, int n_in,
                              void* d_out, int out_size)
{
    const float* x      = (const float*)d_in[0];
    const float* n1g    = (const float*)d_in[1];
    const float* n1b    = (const float*)d_in[2];
    const float* qkv_w  = (const float*)d_in[3];
    const float* qkv_b  = (const float*)d_in[4];
    const float* rpb    = (const float*)d_in[5];
    const float* proj_w = (const float*)d_in[6];
    const float* proj_b = (const float*)d_in[7];
    const float* n2g    = (const float*)d_in[8];
    const float* n2b    = (const float*)d_in[9];
    const float* fc1_w  = (const float*)d_in[10];
    const float* fc1_b  = (const float*)d_in[11];
    const float* fc2_w  = (const float*)d_in[12];
    const float* fc2_b  = (const float*)d_in[13];
    const int*   rel    = (const int*)d_in[14];
    const float* mask   = (const float*)d_in[15];
    float* out = (float*)d_out;

    __nv_bfloat16 *ybf, *qkvbf, *obf, *h1bf, *wbf;
    float *xres;
    cudaGetSymbolAddress((void**)&ybf,   g_ybf);
    cudaGetSymbolAddress((void**)&qkvbf, g_qkvbf);
    cudaGetSymbolAddress((void**)&obf,   g_obf);
    cudaGetSymbolAddress((void**)&h1bf,  g_h1bf);
    cudaGetSymbolAddress((void**)&xres,  g_xres);
    cudaGetSymbolAddress((void**)&wbf,   g_wbf);

    // weights -> bf16
    cvt_k<<<(196608+255)/256, 256>>>(qkv_w,  wbf + OFF_QKV,  196608);
    cvt_k<<<( 65536+255)/256, 256>>>(proj_w, wbf + OFF_PROJ,  65536);
    cvt_k<<<(262144+255)/256, 256>>>(fc1_w,  wbf + OFF_FC1,  262144);
    cvt_k<<<(262144+255)/256, 256>>>(fc2_w,  wbf + OFF_FC2,  262144);

    // 1) LN1 + shift + window partition (gather) -> bf16
    ln_k<true><<<Mtok, 256>>>(x, n1g, n1b, ybf);
    // 2) QKV: (M,256) @ (768,256)^T
    hgemm<0><<<dim3(768/128, Mtok/128), 256>>>(ybf, wbf + OFF_QKV, qkv_b, 256, 768, qkvbf, nullptr);
    // 3) windowed attention
    attn_k<<<BWIN*HEADS, 256>>>(qkvbf, rpb, rel, mask, obf);
    // 4) proj + window reverse + shift + residual (scatter)
    hgemm<3><<<dim3(256/128, Mtok/128), 256>>>(obf, wbf + OFF_PROJ, proj_b, 256, 256, xres, x);
    // 5) LN2 -> bf16
    ln_k<false><<<Mtok, 256>>>(xres, n2g, n2b, ybf);
    // 6) FC1 + gelu -> bf16
    hgemm<1><<<dim3(1024/128, Mtok/128), 256>>>(ybf, wbf + OFF_FC1, fc1_b, 256, 1024, h1bf, nullptr);
    // 7) FC2 + residual -> out
    hgemm<2><<<dim3(256/128, Mtok/128), 256>>>(h1bf, wbf + OFF_FC2, fc2_b, 1024, 256, out, xres);
}

// round 8
// speedup vs baseline: 2.4199x; 1.2289x over previous
#include <cuda_runtime.h>
#include <cuda_bf16.h>
#include <cstdint>
#include <math.h>

#define Bv     64
#define Hh     56
#define Wd     56
#define Cc     256
#define WSZ    7
#define SHIFT  3
#define HEADS  8
#define Nn     49
#define HID    1024
#define Ltok   (Hh*Wd)        // 3136
#define Mtok   (Bv*Ltok)      // 200704
#define BWIN   (Bv*64)        // 4096 windows
#define HD     32

// ---------------- scratch (static device arrays; no cudaMalloc) -------------
__device__ __nv_bfloat16 g_ybf  [(size_t)Mtok*Cc];
__device__ __nv_bfloat16 g_qkvbf[(size_t)Mtok*3*Cc];
__device__ __nv_bfloat16 g_obf  [(size_t)Mtok*Cc];
__device__ __nv_bfloat16 g_h1bf [(size_t)Mtok*HID];
__device__ float         g_xres [(size_t)Mtok*Cc];
__device__ __nv_bfloat16 g_wbf  [786432];   // qkv|proj|fc1|fc2 bf16 weights

#define OFF_QKV  0
#define OFF_PROJ 196608
#define OFF_FC1  262144
#define OFF_FC2  524288

// ---------------- PTX helpers (sm_80-era only; no tcgen05) ------------------
__device__ __forceinline__ uint32_t smem_to_u32(const void* p) {
    uint32_t a;
    asm("{ .reg .u64 t; cvta.to.shared.u64 t, %1; cvt.u32.u64 %0, t; }" : "=r"(a) : "l"(p));
    return a;
}
#define CP_ASYNC16(dst, src) asm volatile("cp.async.cg.shared.global [%0], [%1], 16;" :: "r"((uint32_t)(dst)), "l"(src) : "memory")
#define CP_COMMIT()          asm volatile("cp.async.commit_group;" ::: "memory")
#define CP_WAIT(n)           asm volatile("cp.async.wait_group %0;" :: "n"(n) : "memory")

#define LDSM_X4(r, addr) \
    asm volatile("ldmatrix.sync.aligned.m8n8.x4.shared.b16 {%0,%1,%2,%3}, [%4];" \
        : "=r"((r)[0]),"=r"((r)[1]),"=r"((r)[2]),"=r"((r)[3]) : "r"(addr))

#define MMA16816(c, a, b0, b1) \
    asm volatile("mma.sync.aligned.m16n8k16.row.col.f32.bf16.bf16.f32 " \
        "{%0,%1,%2,%3},{%4,%5,%6,%7},{%8,%9},{%0,%1,%2,%3};" \
        : "+f"((c)[0]),"+f"((c)[1]),"+f"((c)[2]),"+f"((c)[3]) \
        : "r"((a)[0]),"r"((a)[1]),"r"((a)[2]),"r"((a)[3]), "r"(b0),"r"(b1))

// token t (window order) -> pixel row (original order), incl. cyclic shift
__device__ __forceinline__ size_t dest_row(int t) {
    int b_ = t / Nn, n = t - b_*Nn;
    int b  = b_ >> 6, w = b_ & 63;
    int wh = w >> 3, wc = w & 7;
    int i  = n / WSZ, j = n - i*WSZ;
    int sh = wh*WSZ + i + SHIFT; if (sh >= Hh) sh -= Hh;
    int sw = wc*WSZ + j + SHIFT; if (sw >= Wd) sw -= Wd;
    return (size_t)b*Ltok + (size_t)sh*Wd + sw;
}

// ---------------- weight fp32 -> bf16 ---------------------------------------
__global__ void cvt_k(const float* __restrict__ s, __nv_bfloat16* __restrict__ d, int n) {
    int i = blockIdx.x*blockDim.x + threadIdx.x;
    if (i < n) d[i] = __float2bfloat16(s[i]);
}

// ---------------- LayerNorm: warp per token, 8 tokens per block -------------
template<bool MAP>
__global__ __launch_bounds__(256) void ln_k(const float* __restrict__ x,
                                            const float* __restrict__ g,
                                            const float* __restrict__ bta,
                                            __nv_bfloat16* __restrict__ y)
{
    const int warp = threadIdx.x >> 5, lane = threadIdx.x & 31;
    const int t = blockIdx.x*8 + warp;
    size_t src = MAP ? dest_row(t) : (size_t)t;
    const float* xp = x + src*Cc + lane*8;
    float4 a0 = *(const float4*)xp;
    float4 a1 = *(const float4*)(xp + 4);

    float s = a0.x+a0.y+a0.z+a0.w + a1.x+a1.y+a1.z+a1.w;
    #pragma unroll
    for (int o = 16; o; o >>= 1) s += __shfl_xor_sync(0xffffffffu, s, o);
    float mean = s * (1.f/256.f);

    float q =  (a0.x-mean)*(a0.x-mean) + (a0.y-mean)*(a0.y-mean)
             + (a0.z-mean)*(a0.z-mean) + (a0.w-mean)*(a0.w-mean)
             + (a1.x-mean)*(a1.x-mean) + (a1.y-mean)*(a1.y-mean)
             + (a1.z-mean)*(a1.z-mean) + (a1.w-mean)*(a1.w-mean);
    #pragma unroll
    for (int o = 16; o; o >>= 1) q += __shfl_xor_sync(0xffffffffu, q, o);
    float inv = rsqrtf(q*(1.f/256.f) + 1e-5f);

    const float* gp = g + lane*8;
    const float* bp = bta + lane*8;
    __nv_bfloat16 ob[8];
    float v[8] = {a0.x,a0.y,a0.z,a0.w,a1.x,a1.y,a1.z,a1.w};
    #pragma unroll
    for (int j = 0; j < 8; j++)
        ob[j] = __float2bfloat16((v[j]-mean)*inv*gp[j] + bp[j]);
    *(uint4*)(y + (size_t)t*Cc + lane*8) = *(uint4*)ob;
}

// ---------------- HMMA GEMM: C = epi(A[M,K]bf16 @ W[N,K]bf16^T + bias) ------
// CTA tile 128x128, BK=32, 8 warps (4m x 2n), warp tile 32x64, 4-stage pipeline.
#define NSTAGE 4
#define LDK 40                  // padded row stride (halves)
#define SBUF (128*LDK)          // halves per stage per operand
#define GSMEM (NSTAGE*SBUF*2*2) // bytes total (A + B)

template<int EPI>
__global__ __launch_bounds__(256, 2) void hgemm(const __nv_bfloat16* __restrict__ A,
                                                const __nv_bfloat16* __restrict__ W,
                                                const float* __restrict__ bias,
                                                int K, int Ntot,
                                                void* __restrict__ Cout,
                                                const float* __restrict__ res)
{
    extern __shared__ __align__(16) __nv_bfloat16 sm[];
    const uint32_t aB = smem_to_u32(sm);                       // A stages
    const uint32_t bB = aB + NSTAGE*SBUF*2;                    // B stages

    const int tid = threadIdx.x, warp = tid >> 5, lane = tid & 31;
    const int wm = warp & 3, wn = warp >> 2;
    const int bm = blockIdx.y * 128, bn = blockIdx.x * 128;

    const int t8 = lane >> 3, lr = lane & 7;
    const int a_row = wm*32 + (t8 & 1)*8 + lr;
    const int a_col = (t8 >> 1)*8;
    const int b_row = wn*64 + (t8 >> 1)*8 + lr;
    const int b_col = (t8 & 1)*8;

    const int cr = tid >> 2, ccol = (tid & 3) * 8;   // loader: rows cr, cr+64

    float acc[2][8][4];
    #pragma unroll
    for (int mt = 0; mt < 2; mt++)
        #pragma unroll
        for (int nt = 0; nt < 8; nt++)
            #pragma unroll
            for (int j = 0; j < 4; j++) acc[mt][nt][j] = 0.f;

    const int nk = K >> 5;

    // prologue: stages 0..NSTAGE-2
    #pragma unroll
    for (int st = 0; st < NSTAGE-1; st++) {
        const int k0 = st << 5;
        #pragma unroll
        for (int l = 0; l < 2; l++) {
            int r = cr + l*64;
            CP_ASYNC16(aB + (st*SBUF + r*LDK + ccol)*2, A + (size_t)(bm + r)*K + k0 + ccol);
            CP_ASYNC16(bB + (st*SBUF + r*LDK + ccol)*2, W + (size_t)(bn + r)*K + k0 + ccol);
        }
        CP_COMMIT();
    }

    for (int i = 0; i < nk; i++) {
        CP_WAIT(NSTAGE-2);
        __syncthreads();

        const int pf = i + NSTAGE - 1;
        if (pf < nk) {
            const int st = pf % NSTAGE, k0 = pf << 5;
            #pragma unroll
            for (int l = 0; l < 2; l++) {
                int r = cr + l*64;
                CP_ASYNC16(aB + (st*SBUF + r*LDK + ccol)*2, A + (size_t)(bm + r)*K + k0 + ccol);
                CP_ASYNC16(bB + (st*SBUF + r*LDK + ccol)*2, W + (size_t)(bn + r)*K + k0 + ccol);
            }
        }
        CP_COMMIT();

        const int cs = i % NSTAGE;
        const uint32_t aS = aB + cs*SBUF*2;
        const uint32_t bS = bB + cs*SBUF*2;
        #pragma unroll
        for (int ks = 0; ks < 2; ks++) {
            uint32_t afr[2][4], bfr[4][4];
            #pragma unroll
            for (int mt = 0; mt < 2; mt++)
                LDSM_X4(afr[mt], aS + (uint32_t)(((a_row + mt*16)*LDK) + ks*16 + a_col)*2);
            #pragma unroll
            for (int pr = 0; pr < 4; pr++)
                LDSM_X4(bfr[pr], bS + (uint32_t)(((b_row + pr*16)*LDK) + ks*16 + b_col)*2);
            #pragma unroll
            for (int mt = 0; mt < 2; mt++)
                #pragma unroll
                for (int nt = 0; nt < 8; nt++)
                    MMA16816(acc[mt][nt], afr[mt], bfr[nt >> 1][(nt & 1)*2], bfr[nt >> 1][(nt & 1)*2 + 1]);
        }
    }

    // epilogue from register accumulators
    const int qr = lane >> 2, qc = (lane & 3) * 2;
    #pragma unroll
    for (int mt = 0; mt < 2; mt++) {
        #pragma unroll
        for (int h = 0; h < 2; h++) {
            int row = bm + wm*32 + mt*16 + qr + h*8;
            size_t orow = (EPI == 3) ? dest_row(row) : (size_t)row;
            #pragma unroll
            for (int nt = 0; nt < 8; nt++) {
                int col = bn + wn*64 + nt*8 + qc;
                float v0 = acc[mt][nt][h*2 + 0] + bias[col];
                float v1 = acc[mt][nt][h*2 + 1] + bias[col + 1];
                if (EPI == 0) {
                    __nv_bfloat162 p; p.x = __float2bfloat16(v0); p.y = __float2bfloat16(v1);
                    *(__nv_bfloat162*)((__nv_bfloat16*)Cout + (size_t)row*Ntot + col) = p;
                } else if (EPI == 1) {
                    v0 = v0 / (1.f + __expf(-1.702f*v0));
                    v1 = v1 / (1.f + __expf(-1.702f*v1));
                    __nv_bfloat162 p; p.x = __float2bfloat16(v0); p.y = __float2bfloat16(v1);
                    *(__nv_bfloat162*)((__nv_bfloat16*)Cout + (size_t)row*Ntot + col) = p;
                } else {
                    size_t gi = orow*(size_t)Ntot + col;
                    float2 p; p.x = res[gi] + v0; p.y = res[gi + 1] + v1;
                    *(float2*)((float*)Cout + gi) = p;
                }
            }
        }
    }
}

// ---------------- windowed attention (vectorized fp32) ----------------------
#define MP 52   // padded m dimension (multiple of 4)
__global__ __launch_bounds__(256) void attn_k(const __nv_bfloat16* __restrict__ qkv,
                                              const float* __restrict__ rpb,
                                              const int*   __restrict__ rel,
                                              const float* __restrict__ mask,
                                              __nv_bfloat16* __restrict__ o)
{
    int bh = blockIdx.x;
    int b_ = bh >> 3, head = bh & 7;
    __shared__ float q [Nn][HD];
    __shared__ float kt[HD][MP];       // [d][m], padded
    __shared__ float v [Nn][HD];       // [m][d]
    __shared__ float s [Nn][MP];
    int tid = threadIdx.x;
    const float scale = 0.17677669529663687f;

    for (int idx = tid; idx < Nn*HD; idx += 256) {
        int n = idx >> 5, d = idx & 31;
        size_t base = ((size_t)(b_*Nn + n))*768 + head*HD + d;
        q [n][d] = __bfloat162float(qkv[base]) * scale;
        kt[d][n] = __bfloat162float(qkv[base + 256]);
        v [n][d] = __bfloat162float(qkv[base + 512]);
    }
    __syncthreads();

    int wIdx = b_ & 63;
    const float* mrow = mask + (size_t)wIdx*Nn*Nn;
    // QK^T: 49 rows x 13 m-groups of 4
    for (int w = tid; w < Nn*13; w += 256) {
        int n = w / 13, m4 = (w - n*13) * 4;
        float4 acc = make_float4(0.f, 0.f, 0.f, 0.f);
        #pragma unroll
        for (int d = 0; d < HD; d++) {
            float qv = q[n][d];
            float4 kv = *(const float4*)&kt[d][m4];
            acc.x += qv*kv.x; acc.y += qv*kv.y; acc.z += qv*kv.z; acc.w += qv*kv.w;
        }
        float av[4] = {acc.x, acc.y, acc.z, acc.w};
        #pragma unroll
        for (int j = 0; j < 4; j++) {
            int m = m4 + j;
            if (m < Nn) {
                int e = n*Nn + m;
                s[n][m] = av[j] + rpb[rel[e]*HEADS + head] + mrow[e];
            }
        }
    }
    __syncthreads();

    int warp = tid >> 5, lane = tid & 31;
    for (int n = warp; n < Nn; n += 8) {
        float mx = -1e30f;
        for (int m = lane; m < Nn; m += 32) mx = fmaxf(mx, s[n][m]);
        #pragma unroll
        for (int o2 = 16; o2; o2 >>= 1) mx = fmaxf(mx, __shfl_xor_sync(0xffffffffu, mx, o2));
        float sum = 0.f;
        for (int m = lane; m < Nn; m += 32) { float e = __expf(s[n][m]-mx); s[n][m] = e; sum += e; }
        #pragma unroll
        for (int o2 = 16; o2; o2 >>= 1) sum += __shfl_xor_sync(0xffffffffu, sum, o2);
        float inv = 1.f/sum;
        for (int m = lane; m < Nn; m += 32) s[n][m] *= inv;
    }
    __syncthreads();

    // PV: 49 rows x 8 d-groups of 4
    for (int w = tid; w < Nn*8; w += 256) {
        int n = w >> 3, d4 = (w & 7) * 4;
        float4 acc = make_float4(0.f, 0.f, 0.f, 0.f);
        #pragma unroll
        for (int m = 0; m < Nn; m++) {
            float sv = s[n][m];
            float4 vv = *(const float4*)&v[m][d4];
            acc.x += sv*vv.x; acc.y += sv*vv.y; acc.z += sv*vv.z; acc.w += sv*vv.w;
        }
        __nv_bfloat16 ob[4];
        ob[0] = __float2bfloat16(acc.x); ob[1] = __float2bfloat16(acc.y);
        ob[2] = __float2bfloat16(acc.z); ob[3] = __float2bfloat16(acc.w);
        *(uint2*)(o + ((size_t)(b_*Nn + n))*Cc + head*HD + d4) = *(uint2*)ob;
    }
}

// ---------------- launch ----------------------------------------------------
extern "C" void kernel_launch(void* const* d_in, const int* in_sizes, int n_in,
                              void* d_out, int out_size)
{
    const float* x      = (const float*)d_in[0];
    const float* n1g    = (const float*)d_in[1];
    const float* n1b    = (const float*)d_in[2];
    const float* qkv_w  = (const float*)d_in[3];
    const float* qkv_b  = (const float*)d_in[4];
    const float* rpb    = (const float*)d_in[5];
    const float* proj_w = (const float*)d_in[6];
    const float* proj_b = (const float*)d_in[7];
    const float* n2g    = (const float*)d_in[8];
    const float* n2b    = (const float*)d_in[9];
    const float* fc1_w  = (const float*)d_in[10];
    const float* fc1_b  = (const float*)d_in[11];
    const float* fc2_w  = (const float*)d_in[12];
    const float* fc2_b  = (const float*)d_in[13];
    const int*   rel    = (const int*)d_in[14];
    const float* mask   = (const float*)d_in[15];
    float* out = (float*)d_out;

    __nv_bfloat16 *ybf, *qkvbf, *obf, *h1bf, *wbf;
    float *xres;
    cudaGetSymbolAddress((void**)&ybf,   g_ybf);
    cudaGetSymbolAddress((void**)&qkvbf, g_qkvbf);
    cudaGetSymbolAddress((void**)&obf,   g_obf);
    cudaGetSymbolAddress((void**)&h1bf,  g_h1bf);
    cudaGetSymbolAddress((void**)&xres,  g_xres);
    cudaGetSymbolAddress((void**)&wbf,   g_wbf);

    cudaFuncSetAttribute(hgemm<0>, cudaFuncAttributeMaxDynamicSharedMemorySize, GSMEM);
    cudaFuncSetAttribute(hgemm<1>, cudaFuncAttributeMaxDynamicSharedMemorySize, GSMEM);
    cudaFuncSetAttribute(hgemm<2>, cudaFuncAttributeMaxDynamicSharedMemorySize, GSMEM);
    cudaFuncSetAttribute(hgemm<3>, cudaFuncAttributeMaxDynamicSharedMemorySize, GSMEM);

    // weights -> bf16
    cvt_k<<<(196608+255)/256, 256>>>(qkv_w,  wbf + OFF_QKV,  196608);
    cvt_k<<<( 65536+255)/256, 256>>>(proj_w, wbf + OFF_PROJ,  65536);
    cvt_k<<<(262144+255)/256, 256>>>(fc1_w,  wbf + OFF_FC1,  262144);
    cvt_k<<<(262144+255)/256, 256>>>(fc2_w,  wbf + OFF_FC2,  262144);

    // 1) LN1 + shift + window partition (gather) -> bf16
    ln_k<true><<<Mtok/8, 256>>>(x, n1g, n1b, ybf);
    // 2) QKV: (M,256) @ (768,256)^T
    hgemm<0><<<dim3(768/128, Mtok/128), 256, GSMEM>>>(ybf, wbf + OFF_QKV, qkv_b, 256, 768, qkvbf, nullptr);
    // 3) windowed attention
    attn_k<<<BWIN*HEADS, 256>>>(qkvbf, rpb, rel, mask, obf);
    // 4) proj + window reverse + shift + residual (scatter)
    hgemm<3><<<dim3(256/128, Mtok/128), 256, GSMEM>>>(obf, wbf + OFF_PROJ, proj_b, 256, 256, xres, x);
    // 5) LN2 -> bf16
    ln_k<false><<<Mtok/8, 256>>>(xres, n2g, n2b, ybf);
    // 6) FC1 + gelu -> bf16
    hgemm<1><<<dim3(1024/128, Mtok/128), 256, GSMEM>>>(ybf, wbf + OFF_FC1, fc1_b, 256, 1024, h1bf, nullptr);
    // 7) FC2 + residual -> out
    hgemm<2><<<dim3(256/128, Mtok/128), 256, GSMEM>>>(h1bf, wbf + OFF_FC2, fc2_b, 1024, 256, out, xres);
}

// round 10
// speedup vs baseline: 5.2181x; 2.1564x over previous
#include <cuda_runtime.h>
#include <cuda_bf16.h>
#include <cstdint>
#include <math.h>

#define Bv     64
#define Hh     56
#define Wd     56
#define Cc     256
#define WSZ    7
#define SHIFT  3
#define HEADS  8
#define Nn     49
#define HID    1024
#define Ltok   (Hh*Wd)        // 3136
#define Mtok   (Bv*Ltok)      // 200704
#define BWIN   (Bv*64)        // 4096 windows
#define HD     32
#define CBS    56             // padded bias row stride (even -> float2 aligned)

// ---------------- scratch (static device arrays; no cudaMalloc) -------------
__device__ __nv_bfloat16 g_ybf  [(size_t)Mtok*Cc];
__device__ __nv_bfloat16 g_qkvbf[(size_t)Mtok*3*Cc];
__device__ __nv_bfloat16 g_obf  [(size_t)Mtok*Cc];
__device__ __nv_bfloat16 g_h1bf [(size_t)Mtok*HID];
__device__ float         g_xres [(size_t)Mtok*Cc];
__device__ __nv_bfloat16 g_wbf  [786432];   // qkv|proj|fc1|fc2 bf16 weights
__device__ float         g_cbias[64*8*Nn*CBS + 8];  // combined rpb+mask, padded stride

#define OFF_QKV  0
#define OFF_PROJ 196608
#define OFF_FC1  262144
#define OFF_FC2  524288

// ---------------- PTX helpers (sm_80-era only; no tcgen05) ------------------
__device__ __forceinline__ uint32_t smem_to_u32(const void* p) {
    uint32_t a;
    asm("{ .reg .u64 t; cvta.to.shared.u64 t, %1; cvt.u32.u64 %0, t; }" : "=r"(a) : "l"(p));
    return a;
}
#define CP_ASYNC16(dst, src) asm volatile("cp.async.cg.shared.global [%0], [%1], 16;" :: "r"((uint32_t)(dst)), "l"(src) : "memory")
#define CP_COMMIT()          asm volatile("cp.async.commit_group;" ::: "memory")
#define CP_WAIT(n)           asm volatile("cp.async.wait_group %0;" :: "n"(n) : "memory")

#define LDSM_X4(r, addr) \
    asm volatile("ldmatrix.sync.aligned.m8n8.x4.shared.b16 {%0,%1,%2,%3}, [%4];" \
        : "=r"((r)[0]),"=r"((r)[1]),"=r"((r)[2]),"=r"((r)[3]) : "r"(addr))

#define MMA16816(c, a, b0, b1) \
    asm volatile("mma.sync.aligned.m16n8k16.row.col.f32.bf16.bf16.f32 " \
        "{%0,%1,%2,%3},{%4,%5,%6,%7},{%8,%9},{%0,%1,%2,%3};" \
        : "+f"((c)[0]),"+f"((c)[1]),"+f"((c)[2]),"+f"((c)[3]) \
        : "r"((a)[0]),"r"((a)[1]),"r"((a)[2]),"r"((a)[3]), "r"(b0),"r"(b1))

// token t (window order) -> pixel row (original order), incl. cyclic shift
__device__ __forceinline__ size_t dest_row(int t) {
    int b_ = t / Nn, n = t - b_*Nn;
    int b  = b_ >> 6, w = b_ & 63;
    int wh = w >> 3, wc = w & 7;
    int i  = n / WSZ, j = n - i*WSZ;
    int sh = wh*WSZ + i + SHIFT; if (sh >= Hh) sh -= Hh;
    int sw = wc*WSZ + j + SHIFT; if (sw >= Wd) sw -= Wd;
    return (size_t)b*Ltok + (size_t)sh*Wd + sw;
}

// ---------------- weight fp32 -> bf16 ---------------------------------------
__global__ void cvt_k(const float* __restrict__ s, __nv_bfloat16* __restrict__ d, int n) {
    int i = blockIdx.x*blockDim.x + threadIdx.x;
    if (i < n) d[i] = __float2bfloat16(s[i]);
}

// ---------------- combined attention bias (padded stride CBS) ---------------
__global__ void cbias_k(const float* __restrict__ rpb, const int* __restrict__ rel,
                        const float* __restrict__ mask, float* __restrict__ cb) {
    int i = blockIdx.x*blockDim.x + threadIdx.x;
    if (i >= 64*8*Nn*CBS) return;
    int w = i / (8*Nn*CBS);
    int r = i - w*(8*Nn*CBS);
    int h = r / (Nn*CBS);
    int e = r - h*(Nn*CBS);
    int n = e / CBS, m = e - n*CBS;
    cb[i] = (m < Nn) ? rpb[rel[n*Nn + m]*HEADS + h] + mask[w*Nn*Nn + n*Nn + m] : 0.f;
}

// ---------------- LayerNorm: warp per token, 8 tokens per block -------------
template<bool MAP>
__global__ __launch_bounds__(256) void ln_k(const float* __restrict__ x,
                                            const float* __restrict__ g,
                                            const float* __restrict__ bta,
                                            __nv_bfloat16* __restrict__ y)
{
    const int warp = threadIdx.x >> 5, lane = threadIdx.x & 31;
    const int t = blockIdx.x*8 + warp;
    size_t src = MAP ? dest_row(t) : (size_t)t;
    const float* xp = x + src*Cc + lane*8;
    float4 a0 = *(const float4*)xp;
    float4 a1 = *(const float4*)(xp + 4);

    float s = a0.x+a0.y+a0.z+a0.w + a1.x+a1.y+a1.z+a1.w;
    #pragma unroll
    for (int o = 16; o; o >>= 1) s += __shfl_xor_sync(0xffffffffu, s, o);
    float mean = s * (1.f/256.f);

    float q =  (a0.x-mean)*(a0.x-mean) + (a0.y-mean)*(a0.y-mean)
             + (a0.z-mean)*(a0.z-mean) + (a0.w-mean)*(a0.w-mean)
             + (a1.x-mean)*(a1.x-mean) + (a1.y-mean)*(a1.y-mean)
             + (a1.z-mean)*(a1.z-mean) + (a1.w-mean)*(a1.w-mean);
    #pragma unroll
    for (int o = 16; o; o >>= 1) q += __shfl_xor_sync(0xffffffffu, q, o);
    float inv = rsqrtf(q*(1.f/256.f) + 1e-5f);

    const float* gp = g + lane*8;
    const float* bp = bta + lane*8;
    __nv_bfloat16 ob[8];
    float v[8] = {a0.x,a0.y,a0.z,a0.w,a1.x,a1.y,a1.z,a1.w};
    #pragma unroll
    for (int j = 0; j < 8; j++)
        ob[j] = __float2bfloat16((v[j]-mean)*inv*gp[j] + bp[j]);
    *(uint4*)(y + (size_t)t*Cc + lane*8) = *(uint4*)ob;
}

// ---------------- HMMA GEMM: C = epi(A[M,K]bf16 @ W[N,K]bf16^T + bias) ------
#define NSTAGE 4
#define LDK 40
#define SBUF (128*LDK)
#define GSMEM (NSTAGE*SBUF*2*2)

template<int EPI>
__global__ __launch_bounds__(256, 2) void hgemm(const __nv_bfloat16* __restrict__ A,
                                                const __nv_bfloat16* __restrict__ W,
                                                const float* __restrict__ bias,
                                                int K, int Ntot,
                                                void* __restrict__ Cout,
                                                const float* __restrict__ res)
{
    extern __shared__ __align__(16) __nv_bfloat16 sm[];
    const uint32_t aB = smem_to_u32(sm);
    const uint32_t bB = aB + NSTAGE*SBUF*2;

    const int tid = threadIdx.x, warp = tid >> 5, lane = tid & 31;
    const int wm = warp & 3, wn = warp >> 2;
    const int bm = blockIdx.y * 128, bn = blockIdx.x * 128;

    const int t8 = lane >> 3, lr = lane & 7;
    const int a_row = wm*32 + (t8 & 1)*8 + lr;
    const int a_col = (t8 >> 1)*8;
    const int b_row = wn*64 + (t8 >> 1)*8 + lr;
    const int b_col = (t8 & 1)*8;

    const int cr = tid >> 2, ccol = (tid & 3) * 8;

    float acc[2][8][4];
    #pragma unroll
    for (int mt = 0; mt < 2; mt++)
        #pragma unroll
        for (int nt = 0; nt < 8; nt++)
            #pragma unroll
            for (int j = 0; j < 4; j++) acc[mt][nt][j] = 0.f;

    const int nk = K >> 5;

    #pragma unroll
    for (int st = 0; st < NSTAGE-1; st++) {
        const int k0 = st << 5;
        #pragma unroll
        for (int l = 0; l < 2; l++) {
            int r = cr + l*64;
            CP_ASYNC16(aB + (st*SBUF + r*LDK + ccol)*2, A + (size_t)(bm + r)*K + k0 + ccol);
            CP_ASYNC16(bB + (st*SBUF + r*LDK + ccol)*2, W + (size_t)(bn + r)*K + k0 + ccol);
        }
        CP_COMMIT();
    }

    for (int i = 0; i < nk; i++) {
        CP_WAIT(NSTAGE-2);
        __syncthreads();

        const int pf = i + NSTAGE - 1;
        if (pf < nk) {
            const int st = pf % NSTAGE, k0 = pf << 5;
            #pragma unroll
            for (int l = 0; l < 2; l++) {
                int r = cr + l*64;
                CP_ASYNC16(aB + (st*SBUF + r*LDK + ccol)*2, A + (size_t)(bm + r)*K + k0 + ccol);
                CP_ASYNC16(bB + (st*SBUF + r*LDK + ccol)*2, W + (size_t)(bn + r)*K + k0 + ccol);
            }
        }
        CP_COMMIT();

        const int cs = i % NSTAGE;
        const uint32_t aS = aB + cs*SBUF*2;
        const uint32_t bS = bB + cs*SBUF*2;
        #pragma unroll
        for (int ks = 0; ks < 2; ks++) {
            uint32_t afr[2][4], bfr[4][4];
            #pragma unroll
            for (int mt = 0; mt < 2; mt++)
                LDSM_X4(afr[mt], aS + (uint32_t)(((a_row + mt*16)*LDK) + ks*16 + a_col)*2);
            #pragma unroll
            for (int pr = 0; pr < 4; pr++)
                LDSM_X4(bfr[pr], bS + (uint32_t)(((b_row + pr*16)*LDK) + ks*16 + b_col)*2);
            #pragma unroll
            for (int mt = 0; mt < 2; mt++)
                #pragma unroll
                for (int nt = 0; nt < 8; nt++)
                    MMA16816(acc[mt][nt], afr[mt], bfr[nt >> 1][(nt & 1)*2], bfr[nt >> 1][(nt & 1)*2 + 1]);
        }
    }

    const int qr = lane >> 2, qc = (lane & 3) * 2;
    #pragma unroll
    for (int mt = 0; mt < 2; mt++) {
        #pragma unroll
        for (int h = 0; h < 2; h++) {
            int row = bm + wm*32 + mt*16 + qr + h*8;
            size_t orow = (EPI == 3) ? dest_row(row) : (size_t)row;
            #pragma unroll
            for (int nt = 0; nt < 8; nt++) {
                int col = bn + wn*64 + nt*8 + qc;
                float v0 = acc[mt][nt][h*2 + 0] + bias[col];
                float v1 = acc[mt][nt][h*2 + 1] + bias[col + 1];
                if (EPI == 0) {
                    __nv_bfloat162 p; p.x = __float2bfloat16(v0); p.y = __float2bfloat16(v1);
                    *(__nv_bfloat162*)((__nv_bfloat16*)Cout + (size_t)row*Ntot + col) = p;
                } else if (EPI == 1) {
                    v0 = v0 / (1.f + __expf(-1.702f*v0));
                    v1 = v1 / (1.f + __expf(-1.702f*v1));
                    __nv_bfloat162 p; p.x = __float2bfloat16(v0); p.y = __float2bfloat16(v1);
                    *(__nv_bfloat162*)((__nv_bfloat16*)Cout + (size_t)row*Ntot + col) = p;
                } else {
                    size_t gi = orow*(size_t)Ntot + col;
                    float2 p; p.x = res[gi] + v0; p.y = res[gi + 1] + v1;
                    *(float2*)((float*)Cout + gi) = p;
                }
            }
        }
    }
}

// ---------------- HMMA windowed attention -----------------------------------
// block = (window, 4 heads); 4 warps, one head per warp.
// per-head smem (halves): Q[64][40] | K[64][40] | vT[32][72] | P[64][72]
#define AQ0 0
#define AK0 2560
#define AV0 5120
#define AP0 7424
#define AHEADSZ 12032
#define ASMEM (4*AHEADSZ*2)   // 96256 bytes

__global__ __launch_bounds__(128, 2) void attn_k(const __nv_bfloat16* __restrict__ qkv,
                                                 const float* __restrict__ cbias,
                                                 __nv_bfloat16* __restrict__ o)
{
    extern __shared__ __align__(16) __nv_bfloat16 am[];
    const int tid = threadIdx.x, warp = tid >> 5, lane = tid & 31;
    const int hblk = blockIdx.x & 1;       // heads hblk*4 .. +3
    const int b_   = blockIdx.x >> 1;
    const int wIdx = b_ & 63;
    const float scale = 0.17677669529663687f;

    // zero vT + P regions (padding safety)
    for (int u = tid; u < 4*(AHEADSZ - AV0)/8; u += 128) {
        int h = u / ((AHEADSZ - AV0)/8);
        int r = u - h*((AHEADSZ - AV0)/8);
        *(uint4*)(am + h*AHEADSZ + AV0 + r*8) = make_uint4(0,0,0,0);
    }
    __syncthreads();

    // load Q,K (uint4 = 8 halves); 4 heads x 49 rows x 4 groups
    for (int u = tid; u < 4*49*4; u += 128) {
        int h = u / 196, r = u - h*196, n = r >> 2, dg = r & 3;
        int gh = hblk*4 + h;
        size_t src = ((size_t)(b_*Nn + n))*768 + gh*HD + dg*8;
        *(uint4*)(am + h*AHEADSZ + AQ0 + n*40 + dg*8) = *(const uint4*)(qkv + src);
        *(uint4*)(am + h*AHEADSZ + AK0 + n*40 + dg*8) = *(const uint4*)(qkv + src + 256);
    }
    // load V transposed: vT[d][m]
    for (int u = tid; u < 4*49; u += 128) {
        int h = u / 49, m = u - h*49;
        int gh = hblk*4 + h;
        const __nv_bfloat16* vsrc = qkv + ((size_t)(b_*Nn + m))*768 + 512 + gh*HD;
        __nv_bfloat16 vv[32];
        *(uint4*)(vv)      = *(const uint4*)(vsrc);
        *(uint4*)(vv + 8)  = *(const uint4*)(vsrc + 8);
        *(uint4*)(vv + 16) = *(const uint4*)(vsrc + 16);
        *(uint4*)(vv + 24) = *(const uint4*)(vsrc + 24);
        __nv_bfloat16* vdst = am + h*AHEADSZ + AV0;
        #pragma unroll
        for (int d = 0; d < 32; d++) vdst[d*72 + m] = vv[d];
    }
    __syncthreads();

    const int gh = hblk*4 + warp;
    const uint32_t sb = smem_to_u32(am) + warp*AHEADSZ*2;
    const uint32_t qb = sb + AQ0*2, kb = sb + AK0*2, vb = sb + AV0*2, pb = sb + AP0*2;
    const int t8 = lane >> 3, lr = lane & 7;
    const int lrow = lane >> 2, lcp = (lane & 3)*2;

    // ---- QK^T ----
    float s[4][7][4];
    #pragma unroll
    for (int mt = 0; mt < 4; mt++)
        #pragma unroll
        for (int nt = 0; nt < 7; nt++)
            #pragma unroll
            for (int j = 0; j < 4; j++) s[mt][nt][j] = 0.f;

    #pragma unroll
    for (int kt = 0; kt < 2; kt++) {
        uint32_t af[4][4], bf[4][4];
        #pragma unroll
        for (int mt = 0; mt < 4; mt++)
            LDSM_X4(af[mt], qb + (uint32_t)((mt*16 + (t8&1)*8 + lr)*40 + kt*16 + (t8>>1)*8)*2);
        #pragma unroll
        for (int p2 = 0; p2 < 4; p2++)
            LDSM_X4(bf[p2], kb + (uint32_t)((p2*16 + (t8>>1)*8 + lr)*40 + kt*16 + (t8&1)*8)*2);
        #pragma unroll
        for (int mt = 0; mt < 4; mt++)
            #pragma unroll
            for (int nt = 0; nt < 7; nt++)
                MMA16816(s[mt][nt], af[mt], bf[nt>>1][(nt&1)*2], bf[nt>>1][(nt&1)*2 + 1]);
    }

    // ---- scale + bias + mask (padded stride CBS keeps float2 aligned) ----
    const float* cbh = cbias + (size_t)(wIdx*8 + gh)*Nn*CBS;
    #pragma unroll
    for (int mt = 0; mt < 4; mt++) {
        int r1 = mt*16 + lrow, r2 = r1 + 8;
        #pragma unroll
        for (int nt = 0; nt < 7; nt++) {
            int col = nt*8 + lcp;
            float2 bv1 = make_float2(-1e30f, -1e30f), bv2 = make_float2(-1e30f, -1e30f);
            if (col < Nn) {
                if (r1 < Nn) bv1 = *(const float2*)(cbh + r1*CBS + col);
                if (r2 < Nn) bv2 = *(const float2*)(cbh + r2*CBS + col);
            }
            s[mt][nt][0] = (col     < Nn) ? s[mt][nt][0]*scale + bv1.x : -1e30f;
            s[mt][nt][1] = (col + 1 < Nn) ? s[mt][nt][1]*scale + bv1.y : -1e30f;
            s[mt][nt][2] = (col     < Nn) ? s[mt][nt][2]*scale + bv2.x : -1e30f;
            s[mt][nt][3] = (col + 1 < Nn) ? s[mt][nt][3]*scale + bv2.y : -1e30f;
        }
    }

    // ---- softmax (rows on lane groups of 4; reduce via shfl 1,2) ----
    #pragma unroll
    for (int mt = 0; mt < 4; mt++) {
        float mx1 = -1e30f, mx2 = -1e30f;
        #pragma unroll
        for (int nt = 0; nt < 7; nt++) {
            mx1 = fmaxf(mx1, fmaxf(s[mt][nt][0], s[mt][nt][1]));
            mx2 = fmaxf(mx2, fmaxf(s[mt][nt][2], s[mt][nt][3]));
        }
        mx1 = fmaxf(mx1, __shfl_xor_sync(0xffffffffu, mx1, 1));
        mx1 = fmaxf(mx1, __shfl_xor_sync(0xffffffffu, mx1, 2));
        mx2 = fmaxf(mx2, __shfl_xor_sync(0xffffffffu, mx2, 1));
        mx2 = fmaxf(mx2, __shfl_xor_sync(0xffffffffu, mx2, 2));
        float sm1 = 0.f, sm2 = 0.f;
        #pragma unroll
        for (int nt = 0; nt < 7; nt++) {
            s[mt][nt][0] = __expf(s[mt][nt][0] - mx1); sm1 += s[mt][nt][0];
            s[mt][nt][1] = __expf(s[mt][nt][1] - mx1); sm1 += s[mt][nt][1];
            s[mt][nt][2] = __expf(s[mt][nt][2] - mx2); sm2 += s[mt][nt][2];
            s[mt][nt][3] = __expf(s[mt][nt][3] - mx2); sm2 += s[mt][nt][3];
        }
        sm1 += __shfl_xor_sync(0xffffffffu, sm1, 1);
        sm1 += __shfl_xor_sync(0xffffffffu, sm1, 2);
        sm2 += __shfl_xor_sync(0xffffffffu, sm2, 1);
        sm2 += __shfl_xor_sync(0xffffffffu, sm2, 2);
        float i1 = 1.f/sm1, i2 = 1.f/sm2;
        int r1 = mt*16 + lrow, r2 = r1 + 8;
        #pragma unroll
        for (int nt = 0; nt < 7; nt++) {
            int col = nt*8 + lcp;
            __nv_bfloat162 p1, p2;
            p1.x = __float2bfloat16(s[mt][nt][0]*i1);
            p1.y = __float2bfloat16(s[mt][nt][1]*i1);
            p2.x = __float2bfloat16(s[mt][nt][2]*i2);
            p2.y = __float2bfloat16(s[mt][nt][3]*i2);
            *(__nv_bfloat162*)(am + warp*AHEADSZ + AP0 + r1*72 + col) = p1;
            *(__nv_bfloat162*)(am + warp*AHEADSZ + AP0 + r2*72 + col) = p2;
        }
    }
    __syncwarp();

    // ---- PV ----
    float ofr[4][4][4];
    #pragma unroll
    for (int mt = 0; mt < 4; mt++)
        #pragma unroll
        for (int dt = 0; dt < 4; dt++)
            #pragma unroll
            for (int j = 0; j < 4; j++) ofr[mt][dt][j] = 0.f;

    #pragma unroll
    for (int kt = 0; kt < 4; kt++) {
        uint32_t af[4][4], bf[2][4];
        #pragma unroll
        for (int mt = 0; mt < 4; mt++)
            LDSM_X4(af[mt], pb + (uint32_t)((mt*16 + (t8&1)*8 + lr)*72 + kt*16 + (t8>>1)*8)*2);
        #pragma unroll
        for (int p2 = 0; p2 < 2; p2++)
            LDSM_X4(bf[p2], vb + (uint32_t)((p2*16 + (t8>>1)*8 + lr)*72 + kt*16 + (t8&1)*8)*2);
        #pragma unroll
        for (int mt = 0; mt < 4; mt++)
            #pragma unroll
            for (int dt = 0; dt < 4; dt++)
                MMA16816(ofr[mt][dt], af[mt], bf[dt>>1][(dt&1)*2], bf[dt>>1][(dt&1)*2 + 1]);
    }

    // ---- write O ----
    #pragma unroll
    for (int mt = 0; mt < 4; mt++) {
        int r1 = mt*16 + lrow, r2 = r1 + 8;
        #pragma unroll
        for (int dt = 0; dt < 4; dt++) {
            int col = dt*8 + lcp;
            if (r1 < Nn) {
                __nv_bfloat162 p;
                p.x = __float2bfloat16(ofr[mt][dt][0]);
                p.y = __float2bfloat16(ofr[mt][dt][1]);
                *(__nv_bfloat162*)(o + ((size_t)(b_*Nn + r1))*Cc + gh*HD + col) = p;
            }
            if (r2 < Nn) {
                __nv_bfloat162 p;
                p.x = __float2bfloat16(ofr[mt][dt][2]);
                p.y = __float2bfloat16(ofr[mt][dt][3]);
                *(__nv_bfloat162*)(o + ((size_t)(b_*Nn + r2))*Cc + gh*HD + col) = p;
            }
        }
    }
}

// ---------------- launch ----------------------------------------------------
extern "C" void kernel_launch(void* const* d_in, const int* in_sizes, int n_in,
                              void* d_out, int out_size)
{
    const float* x      = (const float*)d_in[0];
    const float* n1g    = (const float*)d_in[1];
    const float* n1b    = (const float*)d_in[2];
    const float* qkv_w  = (const float*)d_in[3];
    const float* qkv_b  = (const float*)d_in[4];
    const float* rpb    = (const float*)d_in[5];
    const float* proj_w = (const float*)d_in[6];
    const float* proj_b = (const float*)d_in[7];
    const float* n2g    = (const float*)d_in[8];
    const float* n2b    = (const float*)d_in[9];
    const float* fc1_w  = (const float*)d_in[10];
    const float* fc1_b  = (const float*)d_in[11];
    const float* fc2_w  = (const float*)d_in[12];
    const float* fc2_b  = (const float*)d_in[13];
    const int*   rel    = (const int*)d_in[14];
    const float* mask   = (const float*)d_in[15];
    float* out = (float*)d_out;

    __nv_bfloat16 *ybf, *qkvbf, *obf, *h1bf, *wbf;
    float *xres, *cb;
    cudaGetSymbolAddress((void**)&ybf,   g_ybf);
    cudaGetSymbolAddress((void**)&qkvbf, g_qkvbf);
    cudaGetSymbolAddress((void**)&obf,   g_obf);
    cudaGetSymbolAddress((void**)&h1bf,  g_h1bf);
    cudaGetSymbolAddress((void**)&xres,  g_xres);
    cudaGetSymbolAddress((void**)&wbf,   g_wbf);
    cudaGetSymbolAddress((void**)&cb,    g_cbias);

    cudaFuncSetAttribute(hgemm<0>, cudaFuncAttributeMaxDynamicSharedMemorySize, GSMEM);
    cudaFuncSetAttribute(hgemm<1>, cudaFuncAttributeMaxDynamicSharedMemorySize, GSMEM);
    cudaFuncSetAttribute(hgemm<2>, cudaFuncAttributeMaxDynamicSharedMemorySize, GSMEM);
    cudaFuncSetAttribute(hgemm<3>, cudaFuncAttributeMaxDynamicSharedMemorySize, GSMEM);
    cudaFuncSetAttribute(attn_k,   cudaFuncAttributeMaxDynamicSharedMemorySize, ASMEM);

    // setup: weights -> bf16, combined attention bias
    cvt_k<<<(196608+255)/256, 256>>>(qkv_w,  wbf + OFF_QKV,  196608);
    cvt_k<<<( 65536+255)/256, 256>>>(proj_w, wbf + OFF_PROJ,  65536);
    cvt_k<<<(262144+255)/256, 256>>>(fc1_w,  wbf + OFF_FC1,  262144);
    cvt_k<<<(262144+255)/256, 256>>>(fc2_w,  wbf + OFF_FC2,  262144);
    cbias_k<<<(64*8*Nn*CBS + 255)/256, 256>>>(rpb, rel, mask, cb);

    // 1) LN1 + shift + window partition (gather) -> bf16
    ln_k<true><<<Mtok/8, 256>>>(x, n1g, n1b, ybf);
    // 2) QKV: (M,256) @ (768,256)^T
    hgemm<0><<<dim3(768/128, Mtok/128), 256, GSMEM>>>(ybf, wbf + OFF_QKV, qkv_b, 256, 768, qkvbf, nullptr);
    // 3) windowed attention (HMMA)
    attn_k<<<BWIN*2, 128, ASMEM>>>(qkvbf, cb, obf);
    // 4) proj + window reverse + shift + residual (scatter)
    hgemm<3><<<dim3(256/128, Mtok/128), 256, GSMEM>>>(obf, wbf + OFF_PROJ, proj_b, 256, 256, xres, x);
    // 5) LN2 -> bf16
    ln_k<false><<<Mtok/8, 256>>>(xres, n2g, n2b, ybf);
    // 6) FC1 + gelu -> bf16
    hgemm<1><<<dim3(1024/128, Mtok/128), 256, GSMEM>>>(ybf, wbf + OFF_FC1, fc1_b, 256, 1024, h1bf, nullptr);
    // 7) FC2 + residual -> out
    hgemm<2><<<dim3(256/128, Mtok/128), 256, GSMEM>>>(h1bf, wbf + OFF_FC2, fc2_b, 1024, 256, out, xres);
}